// round 13
// baseline (speedup 1.0000x reference)
#include <cuda_runtime.h>
#include <cuda_bf16.h>
#include <cstdint>

#define N_LEVELS 14
#define LOG2_T   19
#define T_MASK   ((1u << LOG2_T) - 1u)
#define P1       2654435761u
#define P2       805459861u
#define NTHREADS 128
#define N_MAX    1048576
#define MBITS    6
#define NBINS    (1 << (3 * MBITS))
#define SCAN_TPB    1024
#define SCAN_BLOCKS (NBINS / SCAN_TPB)   // 256

typedef unsigned long long ull;

__device__ int g_count[NBINS];
__device__ int g_bsum[SCAN_BLOCKS];
__device__ int g_key[N_MAX];
__device__ int g_perm[N_MAX];

__device__ __forceinline__ float tanh_fast(float x) {
    float y; asm("tanh.approx.f32 %0, %1;" : "=f"(y) : "f"(x)); return y;
}
__device__ __forceinline__ uint32_t bf2u(float lo, float hi) {
    __nv_bfloat162 t = __floats2bfloat162_rn(lo, hi);
    return *(uint32_t*)&t;
}
__device__ __forceinline__ uint32_t smem_u32(const void* p) {
    uint32_t a; asm("{ .reg .u64 t; cvta.to.shared.u64 t, %1; cvt.u32.u64 %0, t; }" : "=r"(a) : "l"(p));
    return a;
}
__device__ __forceinline__ unsigned morton6(unsigned v) {
    unsigned r = 0;
    #pragma unroll
    for (int b = 0; b < MBITS; b++) r |= ((v >> b) & 1u) << (3 * b);
    return r;
}

#define LDMX4(r0,r1,r2,r3,addr) \
    asm volatile("ldmatrix.sync.aligned.m8n8.x4.shared.b16 {%0,%1,%2,%3}, [%4];" \
        : "=r"(r0),"=r"(r1),"=r"(r2),"=r"(r3) : "r"(addr))
#define LDMX2(r0,r1,addr) \
    asm volatile("ldmatrix.sync.aligned.m8n8.x2.shared.b16 {%0,%1}, [%2];" \
        : "=r"(r0),"=r"(r1) : "r"(addr))
#define MMA16816(d,a,b0,b1) \
    asm volatile("mma.sync.aligned.m16n8k16.row.col.f32.bf16.bf16.f32 " \
        "{%0,%1,%2,%3}, {%4,%5,%6,%7}, {%8,%9}, {%0,%1,%2,%3};" \
        : "+f"((d)[0]),"+f"((d)[1]),"+f"((d)[2]),"+f"((d)[3]) \
        : "r"((a)[0]),"r"((a)[1]),"r"((a)[2]),"r"((a)[3]),"r"(b0),"r"(b1))

// ---- sort pipeline (R9 exact) ----
__global__ void __launch_bounds__(256)
key_kernel(const float* __restrict__ x, const float* __restrict__ bbox, int n)
{
    int i = blockIdx.x * 256 + threadIdx.x;
    if (i >= n) return;
    float lo0 = bbox[0], lo1 = bbox[1], lo2 = bbox[2];
    float hi0 = bbox[3], hi1 = bbox[4], hi2 = bbox[5];
    float xn0 = (x[i * 3 + 0] - lo0) / (hi0 - lo0);
    float xn1 = (x[i * 3 + 1] - lo1) / (hi1 - lo1);
    float xn2 = (x[i * 3 + 2] - lo2) / (hi2 - lo2);
    unsigned gx = min((unsigned)(max(xn0, 0.f) * 64.f), 63u);
    unsigned gy = min((unsigned)(max(xn1, 0.f) * 64.f), 63u);
    unsigned gz = min((unsigned)(max(xn2, 0.f) * 64.f), 63u);
    int key = (int)(morton6(gx) | (morton6(gy) << 1) | (morton6(gz) << 2));
    g_key[i] = key;
    atomicAdd(&g_count[key], 1);
}

__global__ void __launch_bounds__(SCAN_TPB)
scan1_kernel()
{
    __shared__ int red[SCAN_TPB];
    int t = threadIdx.x;
    red[t] = g_count[blockIdx.x * SCAN_TPB + t];
    __syncthreads();
    #pragma unroll
    for (int d = SCAN_TPB / 2; d > 0; d >>= 1) {
        if (t < d) red[t] += red[t + d];
        __syncthreads();
    }
    if (t == 0) g_bsum[blockIdx.x] = red[0];
}

__global__ void __launch_bounds__(SCAN_BLOCKS)
scan2_kernel()
{
    __shared__ int part[SCAN_BLOCKS];
    int t = threadIdx.x;
    int v = g_bsum[t];
    part[t] = v;
    __syncthreads();
    for (int d = 1; d < SCAN_BLOCKS; d <<= 1) {
        int u = (t >= d) ? part[t - d] : 0;
        __syncthreads();
        part[t] += u;
        __syncthreads();
    }
    g_bsum[t] = part[t] - v;
}

__global__ void __launch_bounds__(SCAN_TPB)
scan3_kernel()
{
    __shared__ int part[SCAN_TPB];
    int t = threadIdx.x;
    int gidx = blockIdx.x * SCAN_TPB + t;
    int c = g_count[gidx];
    part[t] = c;
    __syncthreads();
    for (int d = 1; d < SCAN_TPB; d <<= 1) {
        int u = (t >= d) ? part[t - d] : 0;
        __syncthreads();
        part[t] += u;
        __syncthreads();
    }
    g_count[gidx] = g_bsum[blockIdx.x] + part[t] - c;
}

__global__ void __launch_bounds__(256)
scatter_kernel(int n)
{
    int i = blockIdx.x * 256 + threadIdx.x;
    if (i >= n) return;
    int pos = atomicAdd(&g_count[g_key[i]], 1);
    g_perm[pos] = i;
}

// ---- main kernel: sorted gather encode + tensor-core (mma.sync) MLP ----
__global__ void __launch_bounds__(NTHREADS, 5)
deformnet_kernel(const float* __restrict__ x,
                 const float* __restrict__ e,
                 const float* __restrict__ tables,
                 const float* __restrict__ W1, const float* __restrict__ b1,
                 const float* __restrict__ W2, const float* __restrict__ b2,
                 const float* __restrict__ W3, const float* __restrict__ b3,
                 const float* __restrict__ bbox,
                 float* __restrict__ out, int n)
{
    // weights transposed [n][k], bias folded at k==last. strides multiple of 16B.
    __shared__ __align__(16) __nv_bfloat16 sW1[64 * 48];   // [n][k0..47], k36=b1
    __shared__ __align__(16) __nv_bfloat16 sW2[64 * 80];   // [n][k0..79], k64=b2
    __shared__ __align__(16) __nv_bfloat16 sW3[8 * 80];    // [n][k0..79], k64=b3 (n<3)
    __shared__ __align__(16) __nv_bfloat16 sA[128 * 48];   // feature tile, row per point
    __shared__ float sXn[3][NTHREADS];
    __shared__ int   sIdx[NTHREADS];
    __shared__ float sBB[6];

    const int tid = threadIdx.x;
    for (int t = tid; t < 64 * 48; t += NTHREADS) {
        int nn = t / 48, k = t % 48;
        float v = (k < 36) ? W1[k * 64 + nn] : (k == 36 ? b1[nn] : 0.f);
        sW1[t] = __float2bfloat16(v);
    }
    for (int t = tid; t < 64 * 80; t += NTHREADS) {
        int nn = t / 80, k = t % 80;
        float v = (k < 64) ? W2[k * 64 + nn] : (k == 64 ? b2[nn] : 0.f);
        sW2[t] = __float2bfloat16(v);
    }
    for (int t = tid; t < 8 * 80; t += NTHREADS) {
        int nn = t / 80, k = t % 80;
        float v = 0.f;
        if (nn < 3) v = (k < 64) ? W3[k * 3 + nn] : (k == 64 ? b3[nn] : 0.f);
        sW3[t] = __float2bfloat16(v);
    }
    if (tid < 6) sBB[tid] = bbox[tid];
    __syncthreads();

    const int slot  = blockIdx.x * NTHREADS + tid;
    const int cslot = (slot < n) ? slot : (n - 1);
    const int idx   = g_perm[cslot];
    sIdx[tid] = idx;

    const float lo0 = sBB[0], lo1 = sBB[1], lo2 = sBB[2];
    const float hi0 = sBB[3], hi1 = sBB[4], hi2 = sBB[5];

    const float4* e4p = (const float4*)(e + (size_t)idx * 8);
    float4 ea = __ldg(&e4p[0]);
    float4 eb = __ldg(&e4p[1]);

    float xn0 = (x[idx * 3 + 0] - lo0) / (hi0 - lo0);
    float xn1 = (x[idx * 3 + 1] - lo1) / (hi1 - lo1);
    float xn2 = (x[idx * 3 + 2] - lo2) / (hi2 - lo2);
    sXn[0][tid] = xn0; sXn[1][tid] = xn1; sXn[2][tid] = xn2;

    const float res_tab[N_LEVELS] = {16.f, 21.f, 27.f, 36.f, 48.f, 64.f, 84.f,
                                     111.f, 147.f, 194.f, 256.f, 339.f, 447.f, 590.f};
    const ull* __restrict__ tabs = (const ull*)tables;
    char* arow = (char*)sA + tid * 96;

    // ---- encode: 2 levels per batch, 16 gathers in flight; features -> sA row ----
    #pragma unroll
    for (int lp = 0; lp < 7; lp++) {
        float wxs[2], wys[2], wzs[2];
        unsigned hidx[16];
        #pragma unroll
        for (int s = 0; s < 2; s++) {
            const int l = lp * 2 + s;
            const float r = res_tab[l];
            float px = xn0 * r, py = xn1 * r, pz = xn2 * r;
            float bx = floorf(px), by = floorf(py), bz = floorf(pz);
            float fx = px - bx, fy = py - by, fz = pz - bz;
            wxs[s] = fx * fx * (3.f - 2.f * fx);
            wys[s] = fy * fy * (3.f - 2.f * fy);
            wzs[s] = fz * fz * (3.f - 2.f * fz);
            unsigned ix = (unsigned)bx, iy = (unsigned)by, iz = (unsigned)bz;
            unsigned hx0 = ix,      hx1 = ix + 1u;
            unsigned hy0 = iy * P1, hy1 = (iy + 1u) * P1;
            unsigned hz0 = iz * P2, hz1 = (iz + 1u) * P2;
            const unsigned base = (unsigned)l << LOG2_T;
            hidx[s * 8 + 0] = base + ((hx0 ^ hy0 ^ hz0) & T_MASK);
            hidx[s * 8 + 1] = base + ((hx0 ^ hy0 ^ hz1) & T_MASK);
            hidx[s * 8 + 2] = base + ((hx0 ^ hy1 ^ hz0) & T_MASK);
            hidx[s * 8 + 3] = base + ((hx0 ^ hy1 ^ hz1) & T_MASK);
            hidx[s * 8 + 4] = base + ((hx1 ^ hy0 ^ hz0) & T_MASK);
            hidx[s * 8 + 5] = base + ((hx1 ^ hy0 ^ hz1) & T_MASK);
            hidx[s * 8 + 6] = base + ((hx1 ^ hy1 ^ hz0) & T_MASK);
            hidx[s * 8 + 7] = base + ((hx1 ^ hy1 ^ hz1) & T_MASK);
        }
        ull cc[16];
        #pragma unroll
        for (int q = 0; q < 16; q++) cc[q] = __ldg(&tabs[hidx[q]]);

        uint32_t v[2];
        #pragma unroll
        for (int s = 0; s < 2; s++) {
            float wx = wxs[s], wy = wys[s], wz = wzs[s];
            float ux = 1.f - wx, uy = 1.f - wy, uz = 1.f - wz;
            float w00 = ux * uy, w01 = ux * wy, w10 = wx * uy, w11 = wx * wy;
            float cw[8] = { w00 * uz, w00 * wz, w01 * uz, w01 * wz,
                            w10 * uz, w10 * wz, w11 * uz, w11 * wz };
            float a0 = 0.f, a1 = 0.f;
            #pragma unroll
            for (int q = 0; q < 8; q++) {
                float2 c = *(float2*)&cc[s * 8 + q];
                a0 = fmaf(cw[q], c.x, a0);
                a1 = fmaf(cw[q], c.y, a1);
            }
            v[s] = bf2u(a0, a1);
        }
        *(uint2*)(arow + lp * 8) = make_uint2(v[0], v[1]);
    }
    // e features cols 28..35; bias 1.0 at col 36; zeros 37..47
    *(uint2*)(arow + 56) = make_uint2(bf2u(ea.x, ea.y), bf2u(ea.z, ea.w));
    *(uint2*)(arow + 64) = make_uint2(bf2u(eb.x, eb.y), bf2u(eb.z, eb.w));
    *(uint2*)(arow + 72) = make_uint2(0x00003F80u, 0u);   // bf16 1.0, 0, 0, 0
    *(uint2*)(arow + 80) = make_uint2(0u, 0u);
    *(uint2*)(arow + 88) = make_uint2(0u, 0u);

    __syncwarp();

    // ---- tensor-core MLP: warp computes its 32 points ----
    const int lane = tid & 31;
    const int warp = tid >> 5;
    const int q  = lane >> 3;
    const int r8 = lane & 7;
    const uint32_t Abase = smem_u32(sA) + (uint32_t)warp * 32u * 96u;
    const uint32_t W1b = smem_u32(sW1);
    const uint32_t W2b = smem_u32(sW2);
    const uint32_t W3b = smem_u32(sW3);

    const int a_row = ((q & 1) ? 8 : 0) + r8;
    const int a_col = ((q & 2) ? 8 : 0);
    const int b_nrow = ((q & 2) ? 8 : 0) + r8;
    const int b_kcol = ((q & 1) ? 8 : 0);

    uint32_t af[2][3][4];
    #pragma unroll
    for (int mt = 0; mt < 2; mt++)
        #pragma unroll
        for (int s = 0; s < 3; s++) {
            uint32_t addr = Abase + (uint32_t)((mt * 16 + a_row) * 96 + (s * 16 + a_col) * 2);
            LDMX4(af[mt][s][0], af[mt][s][1], af[mt][s][2], af[mt][s][3], addr);
        }

    const uint32_t synth_a = ((lane & 3) == 0) ? 0x00003F80u : 0u;

    // ---- layer 1 ----
    uint32_t hf1[2][4][4];
    #pragma unroll
    for (int t4 = 0; t4 < 4; t4++) {
        float d[2][2][4] = {};
        #pragma unroll
        for (int s = 0; s < 3; s++) {
            uint32_t b0, b1, b2r, b3r;
            uint32_t addr = W1b + (uint32_t)((t4 * 16 + b_nrow) * 96 + (s * 16 + b_kcol) * 2);
            LDMX4(b0, b1, b2r, b3r, addr);
            #pragma unroll
            for (int mt = 0; mt < 2; mt++) {
                MMA16816(d[mt][0], af[mt][s], b0, b1);
                MMA16816(d[mt][1], af[mt][s], b2r, b3r);
            }
        }
        #pragma unroll
        for (int mt = 0; mt < 2; mt++) {
            hf1[mt][t4][0] = bf2u(tanh_fast(d[mt][0][0]), tanh_fast(d[mt][0][1]));
            hf1[mt][t4][1] = bf2u(tanh_fast(d[mt][0][2]), tanh_fast(d[mt][0][3]));
            hf1[mt][t4][2] = bf2u(tanh_fast(d[mt][1][0]), tanh_fast(d[mt][1][1]));
            hf1[mt][t4][3] = bf2u(tanh_fast(d[mt][1][2]), tanh_fast(d[mt][1][3]));
        }
    }

    // ---- layer 2 ----
    uint32_t hf2[2][4][4];
    #pragma unroll
    for (int t4 = 0; t4 < 4; t4++) {
        float d[2][2][4] = {};
        #pragma unroll
        for (int s = 0; s < 5; s++) {
            uint32_t b0, b1, b2r, b3r;
            uint32_t addr = W2b + (uint32_t)((t4 * 16 + b_nrow) * 160 + (s * 16 + b_kcol) * 2);
            LDMX4(b0, b1, b2r, b3r, addr);
            uint32_t asyn[4] = { synth_a, synth_a, 0u, 0u };
            #pragma unroll
            for (int mt = 0; mt < 2; mt++) {
                const uint32_t* a = (s < 4) ? hf1[mt][s] : asyn;
                MMA16816(d[mt][0], a, b0, b1);
                MMA16816(d[mt][1], a, b2r, b3r);
            }
        }
        #pragma unroll
        for (int mt = 0; mt < 2; mt++) {
            hf2[mt][t4][0] = bf2u(tanh_fast(d[mt][0][0]), tanh_fast(d[mt][0][1]));
            hf2[mt][t4][1] = bf2u(tanh_fast(d[mt][0][2]), tanh_fast(d[mt][0][3]));
            hf2[mt][t4][2] = bf2u(tanh_fast(d[mt][1][0]), tanh_fast(d[mt][1][1]));
            hf2[mt][t4][3] = bf2u(tanh_fast(d[mt][1][2]), tanh_fast(d[mt][1][3]));
        }
    }

    // ---- layer 3 ----
    float d3[2][4] = {};
    #pragma unroll
    for (int s = 0; s < 5; s++) {
        uint32_t b0, b1;
        uint32_t addr = W3b + (uint32_t)(r8 * 160 + (s * 16 + b_kcol) * 2);
        LDMX2(b0, b1, addr);
        uint32_t asyn[4] = { synth_a, synth_a, 0u, 0u };
        #pragma unroll
        for (int mt = 0; mt < 2; mt++) {
            const uint32_t* a = (s < 4) ? hf2[mt][s] : asyn;
            MMA16816(d3[mt], a, b0, b1);
        }
    }

    // ---- epilogue ----
    const int g  = lane >> 2;
    const int cp = (lane & 3) * 2;
    #pragma unroll
    for (int mt = 0; mt < 2; mt++) {
        #pragma unroll
        for (int half = 0; half < 2; half++) {
            int sl = warp * 32 + mt * 16 + g + half * 8;
            int gs = blockIdx.x * NTHREADS + sl;
            if (gs < n) {
                float dlo = d3[mt][half * 2 + 0];
                float dhi = d3[mt][half * 2 + 1];
                int oidx = sIdx[sl];
                if (cp == 0) {
                    out[oidx * 3 + 0] = (dlo + sXn[0][sl]) * (hi0 - lo0) + lo0;
                    out[oidx * 3 + 1] = (dhi + sXn[1][sl]) * (hi1 - lo1) + lo1;
                } else if (cp == 2) {
                    out[oidx * 3 + 2] = (dlo + sXn[2][sl]) * (hi2 - lo2) + lo2;
                }
            }
        }
    }
}

extern "C" void kernel_launch(void* const* d_in, const int* in_sizes, int n_in,
                              void* d_out, int out_size)
{
    const float* x      = (const float*)d_in[0];
    const float* e      = (const float*)d_in[1];
    const float* tables = (const float*)d_in[2];
    const float* W1     = (const float*)d_in[3];
    const float* b1     = (const float*)d_in[4];
    const float* W2     = (const float*)d_in[5];
    const float* b2     = (const float*)d_in[6];
    const float* W3     = (const float*)d_in[7];
    const float* b3     = (const float*)d_in[8];
    const float* bbox   = (const float*)d_in[9];
    float* out = (float*)d_out;

    int n = in_sizes[0] / 3;

    void* pCount = nullptr;
    cudaGetSymbolAddress(&pCount, g_count);
    cudaMemsetAsync(pCount, 0, NBINS * sizeof(int), 0);

    int g256 = (n + 255) / 256;
    key_kernel<<<g256, 256>>>(x, bbox, n);
    scan1_kernel<<<SCAN_BLOCKS, SCAN_TPB>>>();
    scan2_kernel<<<1, SCAN_BLOCKS>>>();
    scan3_kernel<<<SCAN_BLOCKS, SCAN_TPB>>>();
    scatter_kernel<<<g256, 256>>>(n);

    int grid = (n + NTHREADS - 1) / NTHREADS;
    deformnet_kernel<<<grid, NTHREADS>>>(x, e, tables, W1, b1, W2, b2, W3, b3, bbox, out, n);
}

// round 14
// speedup vs baseline: 1.0608x; 1.0608x over previous
#include <cuda_runtime.h>
#include <cuda_bf16.h>
#include <cstdint>

#define N_LEVELS 14
#define LOG2_T   19
#define T_MASK   ((1u << LOG2_T) - 1u)
#define P1       2654435761u
#define P2       805459861u
#define NTHREADS 128
#define N_MAX    1048576
#define MBITS    5
#define GRIDRES  (1 << MBITS)            // 32
#define NBINS    (1 << (3 * MBITS))      // 32768 bins
#define SCAN_TPB    1024
#define SCAN_BLOCKS (NBINS / SCAN_TPB)   // 32

typedef unsigned long long ull;

__device__ int g_count[NBINS];
__device__ int g_bsum[SCAN_BLOCKS];
__device__ int g_key[N_MAX];
__device__ int g_perm[N_MAX];

__device__ __forceinline__ float tanh_fast(float x) {
    float y; asm("tanh.approx.f32 %0, %1;" : "=f"(y) : "f"(x)); return y;
}
__device__ __forceinline__ uint32_t bf2u(float lo, float hi) {
    __nv_bfloat162 t = __floats2bfloat162_rn(lo, hi);
    return *(uint32_t*)&t;
}
__device__ __forceinline__ uint32_t smem_u32(const void* p) {
    uint32_t a; asm("{ .reg .u64 t; cvta.to.shared.u64 t, %1; cvt.u32.u64 %0, t; }" : "=r"(a) : "l"(p));
    return a;
}
__device__ __forceinline__ unsigned morton5(unsigned v) {
    unsigned r = 0;
    #pragma unroll
    for (int b = 0; b < MBITS; b++) r |= ((v >> b) & 1u) << (3 * b);
    return r;
}

#define LDMX4(r0,r1,r2,r3,addr) \
    asm volatile("ldmatrix.sync.aligned.m8n8.x4.shared.b16 {%0,%1,%2,%3}, [%4];" \
        : "=r"(r0),"=r"(r1),"=r"(r2),"=r"(r3) : "r"(addr))
#define LDMX2(r0,r1,addr) \
    asm volatile("ldmatrix.sync.aligned.m8n8.x2.shared.b16 {%0,%1}, [%2];" \
        : "=r"(r0),"=r"(r1) : "r"(addr))
#define MMA16816(d,a,b0,b1) \
    asm volatile("mma.sync.aligned.m16n8k16.row.col.f32.bf16.bf16.f32 " \
        "{%0,%1,%2,%3}, {%4,%5,%6,%7}, {%8,%9}, {%0,%1,%2,%3};" \
        : "+f"((d)[0]),"+f"((d)[1]),"+f"((d)[2]),"+f"((d)[3]) \
        : "r"((a)[0]),"r"((a)[1]),"r"((a)[2]),"r"((a)[3]),"r"(b0),"r"(b1))

// ---- sort pipeline (32^3 bins) ----
__global__ void __launch_bounds__(256)
key_kernel(const float* __restrict__ x, const float* __restrict__ bbox, int n)
{
    int i = blockIdx.x * 256 + threadIdx.x;
    if (i >= n) return;
    float lo0 = bbox[0], lo1 = bbox[1], lo2 = bbox[2];
    float hi0 = bbox[3], hi1 = bbox[4], hi2 = bbox[5];
    float xn0 = (x[i * 3 + 0] - lo0) / (hi0 - lo0);
    float xn1 = (x[i * 3 + 1] - lo1) / (hi1 - lo1);
    float xn2 = (x[i * 3 + 2] - lo2) / (hi2 - lo2);
    unsigned gx = min((unsigned)(max(xn0, 0.f) * (float)GRIDRES), (unsigned)(GRIDRES - 1));
    unsigned gy = min((unsigned)(max(xn1, 0.f) * (float)GRIDRES), (unsigned)(GRIDRES - 1));
    unsigned gz = min((unsigned)(max(xn2, 0.f) * (float)GRIDRES), (unsigned)(GRIDRES - 1));
    int key = (int)(morton5(gx) | (morton5(gy) << 1) | (morton5(gz) << 2));
    g_key[i] = key;
    atomicAdd(&g_count[key], 1);
}

__global__ void __launch_bounds__(SCAN_TPB)
scan1_kernel()
{
    __shared__ int red[SCAN_TPB];
    int t = threadIdx.x;
    red[t] = g_count[blockIdx.x * SCAN_TPB + t];
    __syncthreads();
    #pragma unroll
    for (int d = SCAN_TPB / 2; d > 0; d >>= 1) {
        if (t < d) red[t] += red[t + d];
        __syncthreads();
    }
    if (t == 0) g_bsum[blockIdx.x] = red[0];
}

__global__ void __launch_bounds__(32)
scan2_kernel()
{
    int t = threadIdx.x;
    int v = g_bsum[t];
    int s = v;
    #pragma unroll
    for (int d = 1; d < 32; d <<= 1) {
        int u = __shfl_up_sync(0xFFFFFFFF, s, d);
        if (t >= d) s += u;
    }
    g_bsum[t] = s - v;   // exclusive
}

__global__ void __launch_bounds__(SCAN_TPB)
scan3_kernel()
{
    __shared__ int part[SCAN_TPB];
    int t = threadIdx.x;
    int gidx = blockIdx.x * SCAN_TPB + t;
    int c = g_count[gidx];
    part[t] = c;
    __syncthreads();
    for (int d = 1; d < SCAN_TPB; d <<= 1) {
        int u = (t >= d) ? part[t - d] : 0;
        __syncthreads();
        part[t] += u;
        __syncthreads();
    }
    g_count[gidx] = g_bsum[blockIdx.x] + part[t] - c;
}

__global__ void __launch_bounds__(256)
scatter_kernel(int n)
{
    int i = blockIdx.x * 256 + threadIdx.x;
    if (i >= n) return;
    int pos = atomicAdd(&g_count[g_key[i]], 1);
    g_perm[pos] = i;
}

// ---- main kernel: sorted gather encode + tensor-core (mma.sync) MLP (R12 exact) ----
__global__ void __launch_bounds__(NTHREADS, 4)
deformnet_kernel(const float* __restrict__ x,
                 const float* __restrict__ e,
                 const float* __restrict__ tables,
                 const float* __restrict__ W1, const float* __restrict__ b1,
                 const float* __restrict__ W2, const float* __restrict__ b2,
                 const float* __restrict__ W3, const float* __restrict__ b3,
                 const float* __restrict__ bbox,
                 float* __restrict__ out, int n)
{
    __shared__ __align__(16) __nv_bfloat16 sW1[64 * 48];   // [n][k0..47], k36=b1
    __shared__ __align__(16) __nv_bfloat16 sW2[64 * 80];   // [n][k0..79], k64=b2
    __shared__ __align__(16) __nv_bfloat16 sW3[8 * 80];    // [n][k0..79], k64=b3 (n<3)
    __shared__ __align__(16) __nv_bfloat16 sA[128 * 48];   // feature tile
    __shared__ float sXn[3][NTHREADS];
    __shared__ int   sIdx[NTHREADS];
    __shared__ float sBB[6];

    const int tid = threadIdx.x;
    for (int t = tid; t < 64 * 48; t += NTHREADS) {
        int nn = t / 48, k = t % 48;
        float v = (k < 36) ? W1[k * 64 + nn] : (k == 36 ? b1[nn] : 0.f);
        sW1[t] = __float2bfloat16(v);
    }
    for (int t = tid; t < 64 * 80; t += NTHREADS) {
        int nn = t / 80, k = t % 80;
        float v = (k < 64) ? W2[k * 64 + nn] : (k == 64 ? b2[nn] : 0.f);
        sW2[t] = __float2bfloat16(v);
    }
    for (int t = tid; t < 8 * 80; t += NTHREADS) {
        int nn = t / 80, k = t % 80;
        float v = 0.f;
        if (nn < 3) v = (k < 64) ? W3[k * 3 + nn] : (k == 64 ? b3[nn] : 0.f);
        sW3[t] = __float2bfloat16(v);
    }
    if (tid < 6) sBB[tid] = bbox[tid];
    __syncthreads();

    const int slot  = blockIdx.x * NTHREADS + tid;
    const int cslot = (slot < n) ? slot : (n - 1);
    const int idx   = g_perm[cslot];
    sIdx[tid] = idx;

    const float lo0 = sBB[0], lo1 = sBB[1], lo2 = sBB[2];
    const float hi0 = sBB[3], hi1 = sBB[4], hi2 = sBB[5];

    const float4* e4p = (const float4*)(e + (size_t)idx * 8);
    float4 ea = __ldg(&e4p[0]);
    float4 eb = __ldg(&e4p[1]);

    float xn0 = (x[idx * 3 + 0] - lo0) / (hi0 - lo0);
    float xn1 = (x[idx * 3 + 1] - lo1) / (hi1 - lo1);
    float xn2 = (x[idx * 3 + 2] - lo2) / (hi2 - lo2);
    sXn[0][tid] = xn0; sXn[1][tid] = xn1; sXn[2][tid] = xn2;

    const float res_tab[N_LEVELS] = {16.f, 21.f, 27.f, 36.f, 48.f, 64.f, 84.f,
                                     111.f, 147.f, 194.f, 256.f, 339.f, 447.f, 590.f};
    const ull* __restrict__ tabs = (const ull*)tables;
    char* arow = (char*)sA + tid * 96;

    #pragma unroll
    for (int lp = 0; lp < 7; lp++) {
        float wxs[2], wys[2], wzs[2];
        unsigned hidx[16];
        #pragma unroll
        for (int s = 0; s < 2; s++) {
            const int l = lp * 2 + s;
            const float r = res_tab[l];
            float px = xn0 * r, py = xn1 * r, pz = xn2 * r;
            float bx = floorf(px), by = floorf(py), bz = floorf(pz);
            float fx = px - bx, fy = py - by, fz = pz - bz;
            wxs[s] = fx * fx * (3.f - 2.f * fx);
            wys[s] = fy * fy * (3.f - 2.f * fy);
            wzs[s] = fz * fz * (3.f - 2.f * fz);
            unsigned ix = (unsigned)bx, iy = (unsigned)by, iz = (unsigned)bz;
            unsigned hx0 = ix,      hx1 = ix + 1u;
            unsigned hy0 = iy * P1, hy1 = (iy + 1u) * P1;
            unsigned hz0 = iz * P2, hz1 = (iz + 1u) * P2;
            const unsigned base = (unsigned)l << LOG2_T;
            hidx[s * 8 + 0] = base + ((hx0 ^ hy0 ^ hz0) & T_MASK);
            hidx[s * 8 + 1] = base + ((hx0 ^ hy0 ^ hz1) & T_MASK);
            hidx[s * 8 + 2] = base + ((hx0 ^ hy1 ^ hz0) & T_MASK);
            hidx[s * 8 + 3] = base + ((hx0 ^ hy1 ^ hz1) & T_MASK);
            hidx[s * 8 + 4] = base + ((hx1 ^ hy0 ^ hz0) & T_MASK);
            hidx[s * 8 + 5] = base + ((hx1 ^ hy0 ^ hz1) & T_MASK);
            hidx[s * 8 + 6] = base + ((hx1 ^ hy1 ^ hz0) & T_MASK);
            hidx[s * 8 + 7] = base + ((hx1 ^ hy1 ^ hz1) & T_MASK);
        }
        ull cc[16];
        #pragma unroll
        for (int q = 0; q < 16; q++) cc[q] = __ldg(&tabs[hidx[q]]);

        uint32_t v[2];
        #pragma unroll
        for (int s = 0; s < 2; s++) {
            float wx = wxs[s], wy = wys[s], wz = wzs[s];
            float ux = 1.f - wx, uy = 1.f - wy, uz = 1.f - wz;
            float w00 = ux * uy, w01 = ux * wy, w10 = wx * uy, w11 = wx * wy;
            float cw[8] = { w00 * uz, w00 * wz, w01 * uz, w01 * wz,
                            w10 * uz, w10 * wz, w11 * uz, w11 * wz };
            float a0 = 0.f, a1 = 0.f;
            #pragma unroll
            for (int q = 0; q < 8; q++) {
                float2 c = *(float2*)&cc[s * 8 + q];
                a0 = fmaf(cw[q], c.x, a0);
                a1 = fmaf(cw[q], c.y, a1);
            }
            v[s] = bf2u(a0, a1);
        }
        *(uint2*)(arow + lp * 8) = make_uint2(v[0], v[1]);
    }
    *(uint2*)(arow + 56) = make_uint2(bf2u(ea.x, ea.y), bf2u(ea.z, ea.w));
    *(uint2*)(arow + 64) = make_uint2(bf2u(eb.x, eb.y), bf2u(eb.z, eb.w));
    *(uint2*)(arow + 72) = make_uint2(0x00003F80u, 0u);
    *(uint2*)(arow + 80) = make_uint2(0u, 0u);
    *(uint2*)(arow + 88) = make_uint2(0u, 0u);

    __syncwarp();

    const int lane = tid & 31;
    const int warp = tid >> 5;
    const int q  = lane >> 3;
    const int r8 = lane & 7;
    const uint32_t Abase = smem_u32(sA) + (uint32_t)warp * 32u * 96u;
    const uint32_t W1b = smem_u32(sW1);
    const uint32_t W2b = smem_u32(sW2);
    const uint32_t W3b = smem_u32(sW3);

    const int a_row = ((q & 1) ? 8 : 0) + r8;
    const int a_col = ((q & 2) ? 8 : 0);
    const int b_nrow = ((q & 2) ? 8 : 0) + r8;
    const int b_kcol = ((q & 1) ? 8 : 0);

    uint32_t af[2][3][4];
    #pragma unroll
    for (int mt = 0; mt < 2; mt++)
        #pragma unroll
        for (int s = 0; s < 3; s++) {
            uint32_t addr = Abase + (uint32_t)((mt * 16 + a_row) * 96 + (s * 16 + a_col) * 2);
            LDMX4(af[mt][s][0], af[mt][s][1], af[mt][s][2], af[mt][s][3], addr);
        }

    const uint32_t synth_a = ((lane & 3) == 0) ? 0x00003F80u : 0u;

    uint32_t hf1[2][4][4];
    #pragma unroll
    for (int t4 = 0; t4 < 4; t4++) {
        float d[2][2][4] = {};
        #pragma unroll
        for (int s = 0; s < 3; s++) {
            uint32_t b0, b1, b2r, b3r;
            uint32_t addr = W1b + (uint32_t)((t4 * 16 + b_nrow) * 96 + (s * 16 + b_kcol) * 2);
            LDMX4(b0, b1, b2r, b3r, addr);
            #pragma unroll
            for (int mt = 0; mt < 2; mt++) {
                MMA16816(d[mt][0], af[mt][s], b0, b1);
                MMA16816(d[mt][1], af[mt][s], b2r, b3r);
            }
        }
        #pragma unroll
        for (int mt = 0; mt < 2; mt++) {
            hf1[mt][t4][0] = bf2u(tanh_fast(d[mt][0][0]), tanh_fast(d[mt][0][1]));
            hf1[mt][t4][1] = bf2u(tanh_fast(d[mt][0][2]), tanh_fast(d[mt][0][3]));
            hf1[mt][t4][2] = bf2u(tanh_fast(d[mt][1][0]), tanh_fast(d[mt][1][1]));
            hf1[mt][t4][3] = bf2u(tanh_fast(d[mt][1][2]), tanh_fast(d[mt][1][3]));
        }
    }

    uint32_t hf2[2][4][4];
    #pragma unroll
    for (int t4 = 0; t4 < 4; t4++) {
        float d[2][2][4] = {};
        #pragma unroll
        for (int s = 0; s < 5; s++) {
            uint32_t b0, b1, b2r, b3r;
            uint32_t addr = W2b + (uint32_t)((t4 * 16 + b_nrow) * 160 + (s * 16 + b_kcol) * 2);
            LDMX4(b0, b1, b2r, b3r, addr);
            uint32_t asyn[4] = { synth_a, synth_a, 0u, 0u };
            #pragma unroll
            for (int mt = 0; mt < 2; mt++) {
                const uint32_t* a = (s < 4) ? hf1[mt][s] : asyn;
                MMA16816(d[mt][0], a, b0, b1);
                MMA16816(d[mt][1], a, b2r, b3r);
            }
        }
        #pragma unroll
        for (int mt = 0; mt < 2; mt++) {
            hf2[mt][t4][0] = bf2u(tanh_fast(d[mt][0][0]), tanh_fast(d[mt][0][1]));
            hf2[mt][t4][1] = bf2u(tanh_fast(d[mt][0][2]), tanh_fast(d[mt][0][3]));
            hf2[mt][t4][2] = bf2u(tanh_fast(d[mt][1][0]), tanh_fast(d[mt][1][1]));
            hf2[mt][t4][3] = bf2u(tanh_fast(d[mt][1][2]), tanh_fast(d[mt][1][3]));
        }
    }

    float d3[2][4] = {};
    #pragma unroll
    for (int s = 0; s < 5; s++) {
        uint32_t b0, b1;
        uint32_t addr = W3b + (uint32_t)(r8 * 160 + (s * 16 + b_kcol) * 2);
        LDMX2(b0, b1, addr);
        uint32_t asyn[4] = { synth_a, synth_a, 0u, 0u };
        #pragma unroll
        for (int mt = 0; mt < 2; mt++) {
            const uint32_t* a = (s < 4) ? hf2[mt][s] : asyn;
            MMA16816(d3[mt], a, b0, b1);
        }
    }

    const int g  = lane >> 2;
    const int cp = (lane & 3) * 2;
    #pragma unroll
    for (int mt = 0; mt < 2; mt++) {
        #pragma unroll
        for (int half = 0; half < 2; half++) {
            int sl = warp * 32 + mt * 16 + g + half * 8;
            int gs = blockIdx.x * NTHREADS + sl;
            if (gs < n) {
                float dlo = d3[mt][half * 2 + 0];
                float dhi = d3[mt][half * 2 + 1];
                int oidx = sIdx[sl];
                if (cp == 0) {
                    out[oidx * 3 + 0] = (dlo + sXn[0][sl]) * (hi0 - lo0) + lo0;
                    out[oidx * 3 + 1] = (dhi + sXn[1][sl]) * (hi1 - lo1) + lo1;
                } else if (cp == 2) {
                    out[oidx * 3 + 2] = (dlo + sXn[2][sl]) * (hi2 - lo2) + lo2;
                }
            }
        }
    }
}

extern "C" void kernel_launch(void* const* d_in, const int* in_sizes, int n_in,
                              void* d_out, int out_size)
{
    const float* x      = (const float*)d_in[0];
    const float* e      = (const float*)d_in[1];
    const float* tables = (const float*)d_in[2];
    const float* W1     = (const float*)d_in[3];
    const float* b1     = (const float*)d_in[4];
    const float* W2     = (const float*)d_in[5];
    const float* b2     = (const float*)d_in[6];
    const float* W3     = (const float*)d_in[7];
    const float* b3     = (const float*)d_in[8];
    const float* bbox   = (const float*)d_in[9];
    float* out = (float*)d_out;

    int n = in_sizes[0] / 3;

    void* pCount = nullptr;
    cudaGetSymbolAddress(&pCount, g_count);
    cudaMemsetAsync(pCount, 0, NBINS * sizeof(int), 0);

    int g256 = (n + 255) / 256;
    key_kernel<<<g256, 256>>>(x, bbox, n);
    scan1_kernel<<<SCAN_BLOCKS, SCAN_TPB>>>();
    scan2_kernel<<<1, 32>>>();
    scan3_kernel<<<SCAN_BLOCKS, SCAN_TPB>>>();
    scatter_kernel<<<g256, 256>>>(n);

    int grid = (n + NTHREADS - 1) / NTHREADS;
    deformnet_kernel<<<grid, NTHREADS>>>(x, e, tables, W1, b1, W2, b2, W3, b3, bbox, out, n);
}

// round 15
// speedup vs baseline: 1.1033x; 1.0401x over previous
#include <cuda_runtime.h>
#include <cuda_bf16.h>
#include <cstdint>

#define N_LEVELS 14
#define LOG2_T   19
#define T_MASK   ((1u << LOG2_T) - 1u)
#define P1       2654435761u
#define P2       805459861u
#define NTHREADS 128
#define N_MAX    1048576
#define MBITS    6
#define GRIDRES  (1 << MBITS)            // 64
#define NBINS    (1 << (3 * MBITS))      // 262144
#define SCAN_TPB    1024
#define SCAN_BLOCKS (NBINS / SCAN_TPB)   // 256

typedef unsigned long long ull;

__device__ int g_count[NBINS];
__device__ int g_bsum[SCAN_BLOCKS];
__device__ int g_key[N_MAX];
__device__ int g_perm[N_MAX];

__device__ __forceinline__ float tanh_fast(float x) {
    float y; asm("tanh.approx.f32 %0, %1;" : "=f"(y) : "f"(x)); return y;
}
__device__ __forceinline__ uint32_t bf2u(float lo, float hi) {
    __nv_bfloat162 t = __floats2bfloat162_rn(lo, hi);
    return *(uint32_t*)&t;
}
__device__ __forceinline__ uint32_t smem_u32(const void* p) {
    uint32_t a; asm("{ .reg .u64 t; cvta.to.shared.u64 t, %1; cvt.u32.u64 %0, t; }" : "=r"(a) : "l"(p));
    return a;
}
__device__ __forceinline__ unsigned morton6(unsigned v) {
    unsigned r = 0;
    #pragma unroll
    for (int b = 0; b < MBITS; b++) r |= ((v >> b) & 1u) << (3 * b);
    return r;
}

#define LDMX4(r0,r1,r2,r3,addr) \
    asm volatile("ldmatrix.sync.aligned.m8n8.x4.shared.b16 {%0,%1,%2,%3}, [%4];" \
        : "=r"(r0),"=r"(r1),"=r"(r2),"=r"(r3) : "r"(addr))
#define LDMX2(r0,r1,addr) \
    asm volatile("ldmatrix.sync.aligned.m8n8.x2.shared.b16 {%0,%1}, [%2];" \
        : "=r"(r0),"=r"(r1) : "r"(addr))
#define MMA16816(d,a,b0,b1) \
    asm volatile("mma.sync.aligned.m16n8k16.row.col.f32.bf16.bf16.f32 " \
        "{%0,%1,%2,%3}, {%4,%5,%6,%7}, {%8,%9}, {%0,%1,%2,%3};" \
        : "+f"((d)[0]),"+f"((d)[1]),"+f"((d)[2]),"+f"((d)[3]) \
        : "r"((a)[0]),"r"((a)[1]),"r"((a)[2]),"r"((a)[3]),"r"(b0),"r"(b1))

// ---- kernel A: Morton key + histogram ----
__global__ void __launch_bounds__(256)
key_kernel(const float* __restrict__ x, const float* __restrict__ bbox, int n)
{
    int i = blockIdx.x * 256 + threadIdx.x;
    if (i >= n) return;
    float lo0 = bbox[0], lo1 = bbox[1], lo2 = bbox[2];
    float hi0 = bbox[3], hi1 = bbox[4], hi2 = bbox[5];
    float xn0 = (x[i * 3 + 0] - lo0) / (hi0 - lo0);
    float xn1 = (x[i * 3 + 1] - lo1) / (hi1 - lo1);
    float xn2 = (x[i * 3 + 2] - lo2) / (hi2 - lo2);
    unsigned gx = min((unsigned)(max(xn0, 0.f) * (float)GRIDRES), (unsigned)(GRIDRES - 1));
    unsigned gy = min((unsigned)(max(xn1, 0.f) * (float)GRIDRES), (unsigned)(GRIDRES - 1));
    unsigned gz = min((unsigned)(max(xn2, 0.f) * (float)GRIDRES), (unsigned)(GRIDRES - 1));
    int key = (int)(morton6(gx) | (morton6(gy) << 1) | (morton6(gz) << 2));
    g_key[i] = key;
    atomicAdd(&g_count[key], 1);
}

// ---- scan stage 1: per-block totals (warp shuffles) ----
__global__ void __launch_bounds__(SCAN_TPB)
scan1_kernel()
{
    __shared__ int wsum[32];
    int t = threadIdx.x;
    int lane = t & 31, wid = t >> 5;
    int v = g_count[blockIdx.x * SCAN_TPB + t];
    #pragma unroll
    for (int d = 16; d > 0; d >>= 1) v += __shfl_down_sync(0xFFFFFFFF, v, d);
    if (lane == 0) wsum[wid] = v;
    __syncthreads();
    if (t < 32) {
        int s = wsum[t];
        #pragma unroll
        for (int d = 16; d > 0; d >>= 1) s += __shfl_down_sync(0xFFFFFFFF, s, d);
        if (t == 0) g_bsum[blockIdx.x] = s;
    }
}

// ---- scan stage 2: exclusive scan of 256 block sums (1 block) ----
__global__ void __launch_bounds__(SCAN_BLOCKS)
scan2_kernel()
{
    __shared__ int wsum[8];
    int t = threadIdx.x;
    int lane = t & 31, wid = t >> 5;
    int v = g_bsum[t];
    int s = v;
    #pragma unroll
    for (int d = 1; d < 32; d <<= 1) {
        int u = __shfl_up_sync(0xFFFFFFFF, s, d);
        if (lane >= d) s += u;
    }
    if (lane == 31) wsum[wid] = s;
    __syncthreads();
    if (t < 8) {
        int w = wsum[t];
        #pragma unroll
        for (int d = 1; d < 8; d <<= 1) {
            int u = __shfl_up_sync(0xFF, w, d);
            if (t >= d) w += u;
        }
        wsum[t] = w;
    }
    __syncthreads();
    int woff = (wid == 0) ? 0 : wsum[wid - 1];
    g_bsum[t] = woff + s - v;   // exclusive
}

// ---- scan stage 3: block-local exclusive scan + block offset (warp shuffles) ----
__global__ void __launch_bounds__(SCAN_TPB)
scan3_kernel()
{
    __shared__ int wsum[32];
    int t = threadIdx.x;
    int lane = t & 31, wid = t >> 5;
    int gidx = blockIdx.x * SCAN_TPB + t;
    int c = g_count[gidx];
    int s = c;
    #pragma unroll
    for (int d = 1; d < 32; d <<= 1) {
        int u = __shfl_up_sync(0xFFFFFFFF, s, d);
        if (lane >= d) s += u;
    }
    if (lane == 31) wsum[wid] = s;
    __syncthreads();
    if (t < 32) {
        int w = wsum[t];
        #pragma unroll
        for (int d = 1; d < 32; d <<= 1) {
            int u = __shfl_up_sync(0xFFFFFFFF, w, d);
            if (t >= d) w += u;
        }
        wsum[t] = w;
    }
    __syncthreads();
    int woff = (wid == 0) ? 0 : wsum[wid - 1];
    g_count[gidx] = g_bsum[blockIdx.x] + woff + s - c;   // exclusive offset
}

// ---- kernel C: scatter permutation ----
__global__ void __launch_bounds__(256)
scatter_kernel(int n)
{
    int i = blockIdx.x * 256 + threadIdx.x;
    if (i >= n) return;
    int pos = atomicAdd(&g_count[g_key[i]], 1);
    g_perm[pos] = i;
}

// ---- main kernel: sorted gather encode + tensor-core (mma.sync) MLP (R12 exact) ----
__global__ void __launch_bounds__(NTHREADS, 4)
deformnet_kernel(const float* __restrict__ x,
                 const float* __restrict__ e,
                 const float* __restrict__ tables,
                 const float* __restrict__ W1, const float* __restrict__ b1,
                 const float* __restrict__ W2, const float* __restrict__ b2,
                 const float* __restrict__ W3, const float* __restrict__ b3,
                 const float* __restrict__ bbox,
                 float* __restrict__ out, int n)
{
    __shared__ __align__(16) __nv_bfloat16 sW1[64 * 48];
    __shared__ __align__(16) __nv_bfloat16 sW2[64 * 80];
    __shared__ __align__(16) __nv_bfloat16 sW3[8 * 80];
    __shared__ __align__(16) __nv_bfloat16 sA[128 * 48];
    __shared__ float sXn[3][NTHREADS];
    __shared__ int   sIdx[NTHREADS];
    __shared__ float sBB[6];

    const int tid = threadIdx.x;
    for (int t = tid; t < 64 * 48; t += NTHREADS) {
        int nn = t / 48, k = t % 48;
        float v = (k < 36) ? W1[k * 64 + nn] : (k == 36 ? b1[nn] : 0.f);
        sW1[t] = __float2bfloat16(v);
    }
    for (int t = tid; t < 64 * 80; t += NTHREADS) {
        int nn = t / 80, k = t % 80;
        float v = (k < 64) ? W2[k * 64 + nn] : (k == 64 ? b2[nn] : 0.f);
        sW2[t] = __float2bfloat16(v);
    }
    for (int t = tid; t < 8 * 80; t += NTHREADS) {
        int nn = t / 80, k = t % 80;
        float v = 0.f;
        if (nn < 3) v = (k < 64) ? W3[k * 3 + nn] : (k == 64 ? b3[nn] : 0.f);
        sW3[t] = __float2bfloat16(v);
    }
    if (tid < 6) sBB[tid] = bbox[tid];
    __syncthreads();

    const int slot  = blockIdx.x * NTHREADS + tid;
    const int cslot = (slot < n) ? slot : (n - 1);
    const int idx   = g_perm[cslot];
    sIdx[tid] = idx;

    const float lo0 = sBB[0], lo1 = sBB[1], lo2 = sBB[2];
    const float hi0 = sBB[3], hi1 = sBB[4], hi2 = sBB[5];

    const float4* e4p = (const float4*)(e + (size_t)idx * 8);
    float4 ea = __ldg(&e4p[0]);
    float4 eb = __ldg(&e4p[1]);

    float xn0 = (x[idx * 3 + 0] - lo0) / (hi0 - lo0);
    float xn1 = (x[idx * 3 + 1] - lo1) / (hi1 - lo1);
    float xn2 = (x[idx * 3 + 2] - lo2) / (hi2 - lo2);
    sXn[0][tid] = xn0; sXn[1][tid] = xn1; sXn[2][tid] = xn2;

    const float res_tab[N_LEVELS] = {16.f, 21.f, 27.f, 36.f, 48.f, 64.f, 84.f,
                                     111.f, 147.f, 194.f, 256.f, 339.f, 447.f, 590.f};
    const ull* __restrict__ tabs = (const ull*)tables;
    char* arow = (char*)sA + tid * 96;

    #pragma unroll
    for (int lp = 0; lp < 7; lp++) {
        float wxs[2], wys[2], wzs[2];
        unsigned hidx[16];
        #pragma unroll
        for (int s = 0; s < 2; s++) {
            const int l = lp * 2 + s;
            const float r = res_tab[l];
            float px = xn0 * r, py = xn1 * r, pz = xn2 * r;
            float bx = floorf(px), by = floorf(py), bz = floorf(pz);
            float fx = px - bx, fy = py - by, fz = pz - bz;
            wxs[s] = fx * fx * (3.f - 2.f * fx);
            wys[s] = fy * fy * (3.f - 2.f * fy);
            wzs[s] = fz * fz * (3.f - 2.f * fz);
            unsigned ix = (unsigned)bx, iy = (unsigned)by, iz = (unsigned)bz;
            unsigned hx0 = ix,      hx1 = ix + 1u;
            unsigned hy0 = iy * P1, hy1 = (iy + 1u) * P1;
            unsigned hz0 = iz * P2, hz1 = (iz + 1u) * P2;
            const unsigned base = (unsigned)l << LOG2_T;
            hidx[s * 8 + 0] = base + ((hx0 ^ hy0 ^ hz0) & T_MASK);
            hidx[s * 8 + 1] = base + ((hx0 ^ hy0 ^ hz1) & T_MASK);
            hidx[s * 8 + 2] = base + ((hx0 ^ hy1 ^ hz0) & T_MASK);
            hidx[s * 8 + 3] = base + ((hx0 ^ hy1 ^ hz1) & T_MASK);
            hidx[s * 8 + 4] = base + ((hx1 ^ hy0 ^ hz0) & T_MASK);
            hidx[s * 8 + 5] = base + ((hx1 ^ hy0 ^ hz1) & T_MASK);
            hidx[s * 8 + 6] = base + ((hx1 ^ hy1 ^ hz0) & T_MASK);
            hidx[s * 8 + 7] = base + ((hx1 ^ hy1 ^ hz1) & T_MASK);
        }
        ull cc[16];
        #pragma unroll
        for (int q = 0; q < 16; q++) cc[q] = __ldg(&tabs[hidx[q]]);

        uint32_t v[2];
        #pragma unroll
        for (int s = 0; s < 2; s++) {
            float wx = wxs[s], wy = wys[s], wz = wzs[s];
            float ux = 1.f - wx, uy = 1.f - wy, uz = 1.f - wz;
            float w00 = ux * uy, w01 = ux * wy, w10 = wx * uy, w11 = wx * wy;
            float cw[8] = { w00 * uz, w00 * wz, w01 * uz, w01 * wz,
                            w10 * uz, w10 * wz, w11 * uz, w11 * wz };
            float a0 = 0.f, a1 = 0.f;
            #pragma unroll
            for (int q = 0; q < 8; q++) {
                float2 c = *(float2*)&cc[s * 8 + q];
                a0 = fmaf(cw[q], c.x, a0);
                a1 = fmaf(cw[q], c.y, a1);
            }
            v[s] = bf2u(a0, a1);
        }
        *(uint2*)(arow + lp * 8) = make_uint2(v[0], v[1]);
    }
    *(uint2*)(arow + 56) = make_uint2(bf2u(ea.x, ea.y), bf2u(ea.z, ea.w));
    *(uint2*)(arow + 64) = make_uint2(bf2u(eb.x, eb.y), bf2u(eb.z, eb.w));
    *(uint2*)(arow + 72) = make_uint2(0x00003F80u, 0u);
    *(uint2*)(arow + 80) = make_uint2(0u, 0u);
    *(uint2*)(arow + 88) = make_uint2(0u, 0u);

    __syncwarp();

    const int lane = tid & 31;
    const int warp = tid >> 5;
    const int q  = lane >> 3;
    const int r8 = lane & 7;
    const uint32_t Abase = smem_u32(sA) + (uint32_t)warp * 32u * 96u;
    const uint32_t W1b = smem_u32(sW1);
    const uint32_t W2b = smem_u32(sW2);
    const uint32_t W3b = smem_u32(sW3);

    const int a_row = ((q & 1) ? 8 : 0) + r8;
    const int a_col = ((q & 2) ? 8 : 0);
    const int b_nrow = ((q & 2) ? 8 : 0) + r8;
    const int b_kcol = ((q & 1) ? 8 : 0);

    uint32_t af[2][3][4];
    #pragma unroll
    for (int mt = 0; mt < 2; mt++)
        #pragma unroll
        for (int s = 0; s < 3; s++) {
            uint32_t addr = Abase + (uint32_t)((mt * 16 + a_row) * 96 + (s * 16 + a_col) * 2);
            LDMX4(af[mt][s][0], af[mt][s][1], af[mt][s][2], af[mt][s][3], addr);
        }

    const uint32_t synth_a = ((lane & 3) == 0) ? 0x00003F80u : 0u;

    uint32_t hf1[2][4][4];
    #pragma unroll
    for (int t4 = 0; t4 < 4; t4++) {
        float d[2][2][4] = {};
        #pragma unroll
        for (int s = 0; s < 3; s++) {
            uint32_t b0, b1, b2r, b3r;
            uint32_t addr = W1b + (uint32_t)((t4 * 16 + b_nrow) * 96 + (s * 16 + b_kcol) * 2);
            LDMX4(b0, b1, b2r, b3r, addr);
            #pragma unroll
            for (int mt = 0; mt < 2; mt++) {
                MMA16816(d[mt][0], af[mt][s], b0, b1);
                MMA16816(d[mt][1], af[mt][s], b2r, b3r);
            }
        }
        #pragma unroll
        for (int mt = 0; mt < 2; mt++) {
            hf1[mt][t4][0] = bf2u(tanh_fast(d[mt][0][0]), tanh_fast(d[mt][0][1]));
            hf1[mt][t4][1] = bf2u(tanh_fast(d[mt][0][2]), tanh_fast(d[mt][0][3]));
            hf1[mt][t4][2] = bf2u(tanh_fast(d[mt][1][0]), tanh_fast(d[mt][1][1]));
            hf1[mt][t4][3] = bf2u(tanh_fast(d[mt][1][2]), tanh_fast(d[mt][1][3]));
        }
    }

    uint32_t hf2[2][4][4];
    #pragma unroll
    for (int t4 = 0; t4 < 4; t4++) {
        float d[2][2][4] = {};
        #pragma unroll
        for (int s = 0; s < 5; s++) {
            uint32_t b0, b1, b2r, b3r;
            uint32_t addr = W2b + (uint32_t)((t4 * 16 + b_nrow) * 160 + (s * 16 + b_kcol) * 2);
            LDMX4(b0, b1, b2r, b3r, addr);
            uint32_t asyn[4] = { synth_a, synth_a, 0u, 0u };
            #pragma unroll
            for (int mt = 0; mt < 2; mt++) {
                const uint32_t* a = (s < 4) ? hf1[mt][s] : asyn;
                MMA16816(d[mt][0], a, b0, b1);
                MMA16816(d[mt][1], a, b2r, b3r);
            }
        }
        #pragma unroll
        for (int mt = 0; mt < 2; mt++) {
            hf2[mt][t4][0] = bf2u(tanh_fast(d[mt][0][0]), tanh_fast(d[mt][0][1]));
            hf2[mt][t4][1] = bf2u(tanh_fast(d[mt][0][2]), tanh_fast(d[mt][0][3]));
            hf2[mt][t4][2] = bf2u(tanh_fast(d[mt][1][0]), tanh_fast(d[mt][1][1]));
            hf2[mt][t4][3] = bf2u(tanh_fast(d[mt][1][2]), tanh_fast(d[mt][1][3]));
        }
    }

    float d3[2][4] = {};
    #pragma unroll
    for (int s = 0; s < 5; s++) {
        uint32_t b0, b1;
        uint32_t addr = W3b + (uint32_t)(r8 * 160 + (s * 16 + b_kcol) * 2);
        LDMX2(b0, b1, addr);
        uint32_t asyn[4] = { synth_a, synth_a, 0u, 0u };
        #pragma unroll
        for (int mt = 0; mt < 2; mt++) {
            const uint32_t* a = (s < 4) ? hf2[mt][s] : asyn;
            MMA16816(d3[mt], a, b0, b1);
        }
    }

    const int g  = lane >> 2;
    const int cp = (lane & 3) * 2;
    #pragma unroll
    for (int mt = 0; mt < 2; mt++) {
        #pragma unroll
        for (int half = 0; half < 2; half++) {
            int sl = warp * 32 + mt * 16 + g + half * 8;
            int gs = blockIdx.x * NTHREADS + sl;
            if (gs < n) {
                float dlo = d3[mt][half * 2 + 0];
                float dhi = d3[mt][half * 2 + 1];
                int oidx = sIdx[sl];
                if (cp == 0) {
                    out[oidx * 3 + 0] = (dlo + sXn[0][sl]) * (hi0 - lo0) + lo0;
                    out[oidx * 3 + 1] = (dhi + sXn[1][sl]) * (hi1 - lo1) + lo1;
                } else if (cp == 2) {
                    out[oidx * 3 + 2] = (dlo + sXn[2][sl]) * (hi2 - lo2) + lo2;
                }
            }
        }
    }
}

extern "C" void kernel_launch(void* const* d_in, const int* in_sizes, int n_in,
                              void* d_out, int out_size)
{
    const float* x      = (const float*)d_in[0];
    const float* e      = (const float*)d_in[1];
    const float* tables = (const float*)d_in[2];
    const float* W1     = (const float*)d_in[3];
    const float* b1     = (const float*)d_in[4];
    const float* W2     = (const float*)d_in[5];
    const float* b2     = (const float*)d_in[6];
    const float* W3     = (const float*)d_in[7];
    const float* b3     = (const float*)d_in[8];
    const float* bbox   = (const float*)d_in[9];
    float* out = (float*)d_out;

    int n = in_sizes[0] / 3;

    void* pCount = nullptr;
    cudaGetSymbolAddress(&pCount, g_count);
    cudaMemsetAsync(pCount, 0, NBINS * sizeof(int), 0);

    int g256 = (n + 255) / 256;
    key_kernel<<<g256, 256>>>(x, bbox, n);
    scan1_kernel<<<SCAN_BLOCKS, SCAN_TPB>>>();
    scan2_kernel<<<1, SCAN_BLOCKS>>>();
    scan3_kernel<<<SCAN_BLOCKS, SCAN_TPB>>>();
    scatter_kernel<<<g256, 256>>>(n);

    int grid = (n + NTHREADS - 1) / NTHREADS;
    deformnet_kernel<<<grid, NTHREADS>>>(x, e, tables, W1, b1, W2, b2, W3, b3, bbox, out, n);
}